// round 14
// baseline (speedup 1.0000x reference)
#include <cuda_runtime.h>

// Problem dims
#define Bn   256
#define INn  512
#define Hn   256
#define Dn   16
#define Mn   64

#define SPB  4                 // samples per CTA
#define NBLK (Bn / SPB)        // 64 CTAs
#define TPB  128               // threads per CTA (each owns 2 H-columns)
#define W2S_STRIDE 260         // pad to break 16-way LDS conflicts in epilogue

// Scratch (no cudaMalloc allowed)
__device__ float g_w2m[Dn * Hn];   // [d][j] layout: mean over M of W2 column groups
__device__ float g_b2m[Dn];
__device__ float g_partial[NBLK];

// ---------------------------------------------------------------------------
// packed fp32x2 helpers (FFMA2 — only reachable via PTX fma.rn.f32x2)
// ---------------------------------------------------------------------------
__device__ __forceinline__ unsigned long long pack2(float lo, float hi) {
    unsigned long long r;
    asm("mov.b64 %0, {%1, %2};" : "=l"(r) : "f"(lo), "f"(hi));
    return r;
}
__device__ __forceinline__ void fma2(unsigned long long& d,
                                     unsigned long long a,
                                     unsigned long long b) {
    asm("fma.rn.f32x2 %0, %1, %2, %0;" : "+l"(d) : "l"(a), "l"(b));
}
__device__ __forceinline__ float2 unpack2(unsigned long long v) {
    float lo, hi;
    asm("mov.b64 {%0, %1}, %2;" : "=f"(lo), "=f"(hi) : "l"(v));
    return make_float2(lo, hi);
}

// ---------------------------------------------------------------------------
// Kernel A: W2m[d][j] = mean_m W2[j, d*M + m];  b2m[d] = mean_m b2[d*M + m]
// grid 16 x 256
// ---------------------------------------------------------------------------
__global__ __launch_bounds__(256) void w2_reduce_kernel(
    const float* __restrict__ W2, const float* __restrict__ b2)
{
    int t = blockIdx.x * blockDim.x + threadIdx.x;   // 0..4095
    int d = t >> 8;            // t / Hn
    int j = t & (Hn - 1);
    const float4* p = reinterpret_cast<const float4*>(
        W2 + (size_t)j * (Dn * Mn) + d * Mn);
    float s = 0.f;
#pragma unroll
    for (int i = 0; i < Mn / 4; i++) {
        float4 v = p[i];
        s += (v.x + v.y) + (v.z + v.w);
    }
    g_w2m[d * Hn + j] = s * (1.0f / Mn);

    if (t < Dn) {
        const float4* q = reinterpret_cast<const float4*>(b2 + t * Mn);
        float sb = 0.f;
#pragma unroll
        for (int i = 0; i < Mn / 4; i++) {
            float4 v = q[i];
            sb += (v.x + v.y) + (v.z + v.w);
        }
        g_b2m[t] = sb * (1.0f / Mn);
    }
}

// ---------------------------------------------------------------------------
// Kernel B: per-CTA: 4 samples. h = tanh(x@W1+b1); pred = h@W2m + b2m;
// partial[blk] = sum_{s,d} (y - pred)^2
// grid NBLK x TPB
// ---------------------------------------------------------------------------
__global__ __launch_bounds__(TPB) void main_kernel(
    const float* __restrict__ x,  const float* __restrict__ y,
    const float* __restrict__ W1, const float* __restrict__ b1)
{
    __shared__ __align__(16) float xsf[INn * SPB];          // x transposed [k][s], 8KB
    __shared__ __align__(16) float hs[SPB][Hn];             // 4KB
    __shared__ __align__(16) float w2s[Dn * W2S_STRIDE];    // ~16.3KB (padded)
    __shared__ float bs[Dn];
    __shared__ float red[SPB * Dn];

    int tid = threadIdx.x;
    int sbase = blockIdx.x * SPB;

    // stage x rows transposed: xsf[k*SPB + s] = x[sbase+s][k]
    const float* xg = x + (size_t)sbase * INn;
    for (int idx = tid; idx < SPB * INn; idx += TPB) {
        int s = idx >> 9;            // idx / INn
        int k = idx & (INn - 1);
        xsf[k * SPB + s] = xg[idx];
    }
    // stage W2m with padded stride
    for (int idx = tid; idx < Dn * Hn; idx += TPB) {
        int d = idx >> 8;
        int j = idx & (Hn - 1);
        w2s[d * W2S_STRIDE + j] = g_w2m[idx];
    }
    if (tid < Dn) bs[tid] = g_b2m[tid];
    __syncthreads();

    // GEMM: thread owns columns j0=tid, j1=tid+128; 4 samples via 2x f32x2 accs each
    const unsigned long long* xs2 =
        reinterpret_cast<const unsigned long long*>(xsf);
    unsigned long long a01 = 0ULL, a23 = 0ULL;   // col j0, samples (0,1)/(2,3)
    unsigned long long c01 = 0ULL, c23 = 0ULL;   // col j1
    const float* w1p = W1 + tid;

#pragma unroll 4
    for (int k = 0; k < INn; k++) {
        float w0  = w1p[k * Hn];
        float w1v = w1p[k * Hn + 128];
        unsigned long long x01 = xs2[k * 2];
        unsigned long long x23 = xs2[k * 2 + 1];
        unsigned long long ww0 = pack2(w0,  w0);
        unsigned long long ww1 = pack2(w1v, w1v);
        fma2(a01, x01, ww0);
        fma2(a23, x23, ww0);
        fma2(c01, x01, ww1);
        fma2(c23, x23, ww1);
    }

    {
        float bb0 = b1[tid], bb1 = b1[tid + 128];
        float2 v01 = unpack2(a01), v23 = unpack2(a23);
        hs[0][tid] = tanhf(v01.x + bb0);
        hs[1][tid] = tanhf(v01.y + bb0);
        hs[2][tid] = tanhf(v23.x + bb0);
        hs[3][tid] = tanhf(v23.y + bb0);
        v01 = unpack2(c01); v23 = unpack2(c23);
        hs[0][tid + 128] = tanhf(v01.x + bb1);
        hs[1][tid + 128] = tanhf(v01.y + bb1);
        hs[2][tid + 128] = tanhf(v23.x + bb1);
        hs[3][tid + 128] = tanhf(v23.y + bb1);
    }
    __syncthreads();

    // Epilogue: 64 outputs (s,d)
    if (tid < SPB * Dn) {
        int s = tid >> 4, d = tid & 15;
        const float4* wv = reinterpret_cast<const float4*>(&w2s[d * W2S_STRIDE]);
        const float4* hv = reinterpret_cast<const float4*>(&hs[s][0]);
        float p = bs[d];
#pragma unroll 8
        for (int j4 = 0; j4 < Hn / 4; j4++) {
            float4 w = wv[j4];
            float4 h = hv[j4];
            p = fmaf(w.x, h.x, p);
            p = fmaf(w.y, h.y, p);
            p = fmaf(w.z, h.z, p);
            p = fmaf(w.w, h.w, p);
        }
        float diff = y[(sbase + s) * Dn + d] - p;
        red[tid] = diff * diff;
    }
    __syncthreads();

    if (tid == 0) {
        float tot = 0.f;
#pragma unroll
        for (int i = 0; i < SPB * Dn; i++) tot += red[i];
        g_partial[blockIdx.x] = tot;
    }
}

// ---------------------------------------------------------------------------
// Kernel C: deterministic final reduce -> loss = 0.5/B * sum(diff^2)
// ---------------------------------------------------------------------------
__global__ void finalize_kernel(float* __restrict__ out)
{
    float tot = 0.f;
#pragma unroll
    for (int i = 0; i < NBLK; i++) tot += g_partial[i];
    out[0] = (0.5f / (float)Bn) * tot;
}

// ---------------------------------------------------------------------------
// Launch: inputs in setup_inputs() order: x, y, W1, b1, W2, b2
// ---------------------------------------------------------------------------
extern "C" void kernel_launch(void* const* d_in, const int* in_sizes, int n_in,
                              void* d_out, int out_size)
{
    const float* x  = (const float*)d_in[0];
    const float* y  = (const float*)d_in[1];
    const float* W1 = (const float*)d_in[2];
    const float* b1 = (const float*)d_in[3];
    const float* W2 = (const float*)d_in[4];
    const float* b2 = (const float*)d_in[5];

    w2_reduce_kernel<<<(Dn * Hn) / 256, 256>>>(W2, b2);
    main_kernel<<<NBLK, TPB>>>(x, y, W1, b1);
    finalize_kernel<<<1, 1>>>((float*)d_out);
}

// round 15
// speedup vs baseline: 1.6539x; 1.6539x over previous
#include <cuda_runtime.h>

// Problem dims
#define Bn   256
#define INn  512
#define Hn   256
#define Dn   16
#define Mn   64

#define SPB  4                  // samples per CTA
#define NBLK (Bn / SPB)         // 64 CTAs (single wave on 148+ SMs)
#define TPB  256                // 8 warps -> 2 warps/SMSP
#define W2S_STRIDE 260          // pad: break LDS conflicts in epilogue
#define XD_STRIDE  5            // u64 stride per k (pad: break STS conflicts)

// Scratch (no cudaMalloc allowed)
__device__ float g_w2m[Dn * Hn];
__device__ float g_partial[NBLK];
__device__ unsigned int g_c1;   // w2m-ready arrivals
__device__ unsigned int g_c2;   // partial-ready arrivals

// ---------------------------------------------------------------------------
// packed fp32x2 helpers (FFMA2 — only reachable via PTX fma.rn.f32x2)
// ---------------------------------------------------------------------------
__device__ __forceinline__ unsigned long long pack2(float lo, float hi) {
    unsigned long long r;
    asm("mov.b64 %0, {%1, %2};" : "=l"(r) : "f"(lo), "f"(hi));
    return r;
}
__device__ __forceinline__ void fma2(unsigned long long& d,
                                     unsigned long long a,
                                     unsigned long long b) {
    asm("fma.rn.f32x2 %0, %1, %2, %0;" : "+l"(d) : "l"(a), "l"(b));
}

// ---------------------------------------------------------------------------
// Single fused kernel.
//  P1: cross-CTA W2 column-group mean  (each CTA owns 64 of 4096 (d,j) pairs)
//  P2: stage x (duplicated f32x2) to SMEM
//  P3: GEMM h_pre = x @ W1  (K split 4 ways across warps, FFMA2 core)
//  P4: combine k-partials + b1 + tanh
//  P5: spin for W2m (already done by now), pred = h @ W2m + b2m, sq-err
//  P6: last CTA reduces partials -> loss, resets counters
// ---------------------------------------------------------------------------
__global__ __launch_bounds__(TPB) void fused_kernel(
    const float* __restrict__ x,  const float* __restrict__ y,
    const float* __restrict__ W1, const float* __restrict__ b1,
    const float* __restrict__ W2, const float* __restrict__ b2,
    float* __restrict__ out)
{
    __shared__ __align__(16) unsigned long long xd[INn * XD_STRIDE]; // 20KB; reused for partials
    __shared__ __align__(16) float w2s[Dn * W2S_STRIDE];             // ~16.3KB
    __shared__ __align__(16) float hs[SPB][Hn];                      // 4KB
    __shared__ float bs[Dn];
    __shared__ float red[SPB * Dn];

    const int tid = threadIdx.x;
    const int blk = blockIdx.x;

    // ---- P1: this CTA's slice of W2m: pairs [blk*64, blk*64+64) -----------
    {
        int pair = blk * 64 + (tid >> 2);      // (d,j): pair = d*256 + j
        int d = pair >> 8;
        int j = pair & (Hn - 1);
        int q = tid & 3;                       // quarter of M
        const float4* p = reinterpret_cast<const float4*>(
            W2 + (size_t)j * (Dn * Mn) + d * Mn + q * 16);
        float s = 0.f;
#pragma unroll
        for (int i = 0; i < 4; i++) { float4 v = p[i]; s += (v.x + v.y) + (v.z + v.w); }
        s += __shfl_down_sync(0xFFFFFFFFu, s, 1);
        s += __shfl_down_sync(0xFFFFFFFFu, s, 2);
        if (q == 0) {
            g_w2m[pair] = s * (1.0f / Mn);
            __threadfence();                   // make slice visible device-wide
        }
    }
    // b2m computed locally per CTA (4KB read, avoids a dependency)
    if (tid < Dn) {
        const float4* q = reinterpret_cast<const float4*>(b2 + tid * Mn);
        float sb = 0.f;
#pragma unroll
        for (int i = 0; i < Mn / 4; i++) { float4 v = q[i]; sb += (v.x + v.y) + (v.z + v.w); }
        bs[tid] = sb * (1.0f / Mn);
    }
    __syncthreads();
    if (tid == 0) atomicAdd(&g_c1, 1u);        // arrive: our W2m slice is published

    // ---- P2: stage x rows as duplicated f32x2: xd[k*5 + s] = (x,x) --------
    const float* xg = x + (size_t)(blk * SPB) * INn;
    for (int idx = tid; idx < SPB * INn; idx += TPB) {
        int s = idx >> 9;                      // idx / INn
        int k = idx & (INn - 1);
        float v = xg[idx];
        xd[k * XD_STRIDE + s] = pack2(v, v);
    }
    __syncthreads();

    // ---- P3: GEMM. thread = (kgroup 0..3, colquad 0..63) -------------------
    const int kg = tid >> 6;
    const int cq = tid & 63;
    unsigned long long acc[SPB][2];
#pragma unroll
    for (int s = 0; s < SPB; s++) { acc[s][0] = 0ULL; acc[s][1] = 0ULL; }

    const int k0 = kg * (INn / 4);
#pragma unroll 8
    for (int k = k0; k < k0 + INn / 4; k++) {
        // 4 W1 columns in one LDG.128, landing directly as two packed f32x2
        ulonglong2 w = *reinterpret_cast<const ulonglong2*>(
            W1 + (size_t)k * Hn + cq * 4);
#pragma unroll
        for (int s = 0; s < SPB; s++) {
            unsigned long long xs = xd[k * XD_STRIDE + s];   // LDS.64 broadcast
            fma2(acc[s][0], w.x, xs);
            fma2(acc[s][1], w.y, xs);
        }
    }
    __syncthreads();                           // xd reads done; reuse as partials

    // dump k-group partials: part[(kg*64+cq)*8 + s*2 + p]
    unsigned long long* part = xd;
#pragma unroll
    for (int s = 0; s < SPB; s++) {
        part[(kg * 64 + cq) * 8 + s * 2 + 0] = acc[s][0];
        part[(kg * 64 + cq) * 8 + s * 2 + 1] = acc[s][1];
    }
    __syncthreads();

    // ---- P4: combine 4 k-groups + bias + tanh: thread t -> column j=t -----
    {
        int j = tid;
        int cq2 = j >> 2, c = j & 3, p = c >> 1, h = c & 1;
        const float* pf = reinterpret_cast<const float*>(part);
        float bb = b1[j];
#pragma unroll
        for (int s = 0; s < SPB; s++) {
            float v = bb;
#pragma unroll
            for (int g = 0; g < 4; g++)
                v += pf[((g * 64 + cq2) * 8 + s * 2 + p) * 2 + h];
            hs[s][j] = tanhf(v);
        }
    }

    // ---- P5: wait for global W2m (long since done), stage + project -------
    if (tid == 0) {
        while (atomicAdd(&g_c1, 0u) < NBLK) { }
        __threadfence();
    }
    __syncthreads();                           // also covers hs writes
    for (int idx = tid; idx < Dn * Hn; idx += TPB) {
        int d = idx >> 8, j = idx & (Hn - 1);
        w2s[d * W2S_STRIDE + j] = __ldcg(&g_w2m[idx]);
    }
    __syncthreads();

    if (tid < SPB * Dn) {
        int s = tid >> 4, d = tid & 15;
        const float4* wv = reinterpret_cast<const float4*>(&w2s[d * W2S_STRIDE]);
        const float4* hv = reinterpret_cast<const float4*>(&hs[s][0]);
        float pacc = bs[d];
#pragma unroll 8
        for (int j4 = 0; j4 < Hn / 4; j4++) {
            float4 w = wv[j4], hh = hv[j4];
            pacc = fmaf(w.x, hh.x, pacc);
            pacc = fmaf(w.y, hh.y, pacc);
            pacc = fmaf(w.z, hh.z, pacc);
            pacc = fmaf(w.w, hh.w, pacc);
        }
        float diff = y[(blk * SPB + s) * Dn + d] - pacc;
        red[tid] = diff * diff;
    }
    __syncthreads();

    // ---- P6: CTA partial, last CTA finalizes + resets counters ------------
    if (tid == 0) {
        float tot = 0.f;
#pragma unroll
        for (int i = 0; i < SPB * Dn; i++) tot += red[i];
        g_partial[blk] = tot;
        __threadfence();
        unsigned int old = atomicAdd(&g_c2, 1u);
        if (old == NBLK - 1) {                 // last arrival: everyone published
            __threadfence();
            float t2 = 0.f;
#pragma unroll
            for (int i = 0; i < NBLK; i++) t2 += __ldcg(&g_partial[i]);
            out[0] = (0.5f / (float)Bn) * t2;
            __threadfence();
            g_c1 = 0u;                         // reset for next launch/replay
            g_c2 = 0u;
        }
    }
}

// ---------------------------------------------------------------------------
// Launch: inputs in setup_inputs() order: x, y, W1, b1, W2, b2
// ---------------------------------------------------------------------------
extern "C" void kernel_launch(void* const* d_in, const int* in_sizes, int n_in,
                              void* d_out, int out_size)
{
    const float* x  = (const float*)d_in[0];
    const float* y  = (const float*)d_in[1];
    const float* W1 = (const float*)d_in[2];
    const float* b1 = (const float*)d_in[3];
    const float* W2 = (const float*)d_in[4];
    const float* b2 = (const float*)d_in[5];

    fused_kernel<<<NBLK, TPB>>>(x, y, W1, b1, W2, b2, (float*)d_out);
}